// round 15
// baseline (speedup 1.0000x reference)
#include <cuda_runtime.h>
#include <cuda_fp16.h>
#include <math.h>
#include <stdint.h>

// ---------------- problem constants ----------------
#define Bv 16
#define Nv 128
#define Dv 256
#define Hv 8
#define BM (Bv*Nv)                               // 2048 (b,m) pairs
#define EDGE_ELEMS ((size_t)Bv*Nv*Nv*Dv)         // 67108864
#define INV_SQRT_DK 0.17677669529663688f

// ---------------- device scratch (no runtime alloc) ----------------
__device__ float g_WqT[Dv*Dv];
__device__ float g_WvT[Dv*Dv];
__device__ uint4 g_qWfrag[(size_t)BM*512];        // per-bm hi/lo score B fragments
__device__ __half2 g_vprojP[(size_t)Bv*64*Dv];    // n-paired half2: [b*64+n2][d]
__device__ __half2 g_WnTp[128*Dv];                // j-paired half2: [j2][d]
// B fragments as tile-pairs: [(kt*16 + tp)*32 + lane] = (t0.b0,t0.b1,t1.b0,t1.b1)
__device__ uint4 g_fragK4[16*16*32];
__device__ uint4 g_fragE4[16*16*32];

// fast exact-identity mish: x*tanh(log1p(e^x)) == x*(u^2-1)/(u^2+1), u=1+e^x
__device__ __forceinline__ float mishf(float x) {
    if (x > 20.0f) return x;
    float t  = __expf(x);
    float u  = 1.0f + t;
    float u2 = u * u;
    return x * __fdividef(u2 - 1.0f, u2 + 1.0f);
}
__device__ __forceinline__ unsigned h2u(__half a, __half b) {
    return (unsigned)__half_as_ushort(a) | ((unsigned)__half_as_ushort(b) << 16);
}
__device__ __forceinline__ unsigned h2pack(__half2 h) {
    return *reinterpret_cast<unsigned*>(&h);
}
__device__ __forceinline__ uint32_t smem_u32(const void* p) {
    uint32_t a;
    asm("{ .reg .u64 t; cvta.to.shared.u64 t, %1; cvt.u32.u64 %0, t; }" : "=r"(a) : "l"(p));
    return a;
}
__device__ __forceinline__ void mma16816(float* d, const unsigned* a,
                                         unsigned b0, unsigned b1) {
    asm volatile(
        "mma.sync.aligned.m16n8k16.row.col.f32.f16.f16.f32 "
        "{%0,%1,%2,%3},{%4,%5,%6,%7},{%8,%9},{%0,%1,%2,%3};"
        : "+f"(d[0]), "+f"(d[1]), "+f"(d[2]), "+f"(d[3])
        : "r"(a[0]), "r"(a[1]), "r"(a[2]), "r"(a[3]), "r"(b0), "r"(b1));
}
__device__ __forceinline__ void ldsm_x4(unsigned* a, uint32_t addr) {
    asm volatile("ldmatrix.sync.aligned.m8n8.x4.shared.b16 {%0,%1,%2,%3}, [%4];"
        : "=r"(a[0]), "=r"(a[1]), "=r"(a[2]), "=r"(a[3]) : "r"(addr));
}
__device__ __forceinline__ void hl_split(float x0, float x1, unsigned& hi, unsigned& lo) {
    __half2 h = __floats2half2_rn(x0, x1);
    float2 r = __half22float2(h);
    __half2 l = __floats2half2_rn(x0 - r.x, x1 - r.y);
    hi = h2pack(h); lo = h2pack(l);
}

// ---------------- K1a: transposes + Wn pack (256 blocks x 256) ----------------
__global__ void wprep_a_kernel(const float* __restrict__ Wq, const float* __restrict__ Wv,
                               const float* __restrict__ Wn) {
    int blk = blockIdx.x, tid = threadIdx.x;
    if (blk < 128) {
        int which = blk >> 6, t2 = blk & 63;
        const float* src = (which == 0) ? Wq : Wv;
        float* dst = (which == 0) ? g_WqT : g_WvT;
        __shared__ float t[32][33];
        int x0 = (t2 & 7) * 32, y0 = (t2 >> 3) * 32;
        int tx = tid & 31, ty = tid >> 5;
        #pragma unroll
        for (int i = 0; i < 32; i += 8) t[ty + i][tx] = src[(y0 + ty + i) * Dv + x0 + tx];
        __syncthreads();
        #pragma unroll
        for (int i = 0; i < 32; i += 8) dst[(x0 + ty + i) * Dv + y0 + tx] = t[tx][ty + i];
    } else {
        int e = (blk - 128) * 256 + tid;          // 0..32767
        int j2 = e >> 8, d = e & 255;
        g_WnTp[e] = __floats2half2_rn(Wn[d * Dv + 2 * j2], Wn[d * Dv + 2 * j2 + 1]);
    }
}

// ---------------- K1b: Wk/We MMA fragments (64 blocks x 256) ----------------
__global__ void wprep_b_kernel(const float* __restrict__ Wk, const float* __restrict__ We) {
    int g = blockIdx.x * 256 + threadIdx.x;       // 0..16383
    int mat = g >> 13;
    int r = g & 8191;
    int kt = r >> 9, tp = (r >> 5) & 15, lane = r & 31;
    const float* W = mat ? We : Wk;
    int k0 = kt * 16 + (lane & 3) * 2;
    int n0 = (2 * tp) * 8 + (lane >> 2);
    int n1 = n0 + 8;
    uint4 f;
    f.x = h2u(__float2half_rn(W[n0 * Dv + k0]),     __float2half_rn(W[n0 * Dv + k0 + 1]));
    f.y = h2u(__float2half_rn(W[n0 * Dv + k0 + 8]), __float2half_rn(W[n0 * Dv + k0 + 9]));
    f.z = h2u(__float2half_rn(W[n1 * Dv + k0]),     __float2half_rn(W[n1 * Dv + k0 + 1]));
    f.w = h2u(__float2half_rn(W[n1 * Dv + k0 + 8]), __float2half_rn(W[n1 * Dv + k0 + 9]));
    if (mat) g_fragE4[r] = f;
    else     g_fragK4[r] = f;
}

// ---------------- K2: q/v projections + qW score fragments (256 CTAs x 8 bm) ----------------
__global__ void __launch_bounds__(256) prep2_kernel(
    const float* __restrict__ qn, const float* __restrict__ vn,
    const float* __restrict__ Wk,
    const float* __restrict__ bq, const float* __restrict__ bv)
{
    __shared__ float sIn[8 * 256];
    __shared__ float sQp[8 * 256];
    int tid = threadIdx.x;
    int bm0 = blockIdx.x * 8;

    // q projection (8 rows)
    for (int e = tid; e < 8 * 256; e += 256) sIn[e] = qn[(size_t)bm0 * 256 + e];
    __syncthreads();
    {
        float acc[8];
        float bqv = bq[tid];
        #pragma unroll
        for (int r = 0; r < 8; ++r) acc[r] = bqv;
        #pragma unroll 8
        for (int j = 0; j < 256; ++j) {
            float w = g_WqT[j * 256 + tid];
            #pragma unroll
            for (int r = 0; r < 8; ++r) acc[r] += sIn[r * 256 + j] * w;
        }
        #pragma unroll
        for (int r = 0; r < 8; ++r) sQp[r * 256 + tid] = acc[r];
    }
    __syncthreads();
    // v projection -> packed half2 pairs (8 rows = 4 n2-pairs)
    for (int e = tid; e < 8 * 256; e += 256) sIn[e] = vn[(size_t)bm0 * 256 + e];
    __syncthreads();
    {
        float acc[8];
        float bvv = bv[tid];
        #pragma unroll
        for (int r = 0; r < 8; ++r) acc[r] = bvv;
        #pragma unroll 8
        for (int j = 0; j < 256; ++j) {
            float w = g_WvT[j * 256 + tid];
            #pragma unroll
            for (int r = 0; r < 8; ++r) acc[r] += sIn[r * 256 + j] * w;
        }
        int b = bm0 >> 7, n2base = (bm0 & 127) >> 1;
        #pragma unroll
        for (int i = 0; i < 4; ++i)
            g_vprojP[((size_t)b * 64 + n2base + i) * 256 + tid] =
                __floats2half2_rn(acc[2 * i], acc[2 * i + 1]);
    }
    // qW fold per head -> transpose via sIn -> emit score fragments directly
    #pragma unroll 1
    for (int h = 0; h < 8; ++h) {
        float acc[8];
        #pragma unroll
        for (int r = 0; r < 8; ++r) acc[r] = 0.0f;
        #pragma unroll 8
        for (int dk = 0; dk < 32; ++dk) {
            float w = Wk[(h * 32 + dk) * 256 + tid];
            #pragma unroll
            for (int r = 0; r < 8; ++r) acc[r] += sQp[r * 256 + h * 32 + dk] * w;
        }
        __syncthreads();   // prior sIn readers (fragment step of h-1) done
        #pragma unroll
        for (int r = 0; r < 8; ++r) sIn[r * 256 + tid] = acc[r] * INV_SQRT_DK;
        __syncthreads();
        // 512 fragment entries for this head (64 per bm: 16 kt x 4 lanes)
        #pragma unroll
        for (int i = 0; i < 2; ++i) {
            int e = tid + i * 256;            // 0..511
            int bmr = e >> 6, rem = e & 63;
            int kt = rem >> 2, lq = rem & 3;
            int k0 = kt * 16 + lq * 2;
            const float* qh = &sIn[bmr * 256];
            uint4 f;
            hl_split(qh[k0],     qh[k0 + 1], f.x, f.z);
            hl_split(qh[k0 + 8], qh[k0 + 9], f.y, f.w);
            g_qWfrag[(size_t)(bm0 + bmr) * 512 + kt * 32 + 4 * h + lq] = f;
        }
    }
}

// ---------------- K3: fused main kernel: 2048 CTAs x 512 threads, 2 CTAs/SM ----------------
#define PITCH 264
#define F_SA_OFF   0                              // 128*264*2 = 67584
#define F_SC_OFF   67584                          // 8192: [0..4K) sAttn/partial0, [4K..8K) partial1 / node partials
#define F_ND_OFF   (F_SC_OFF + 8192)              // 1024 (combined node vector)
#define F_BK_OFF   (F_ND_OFF + 1024)              // 1024
#define F_BE_OFF   (F_BK_OFF + 1024)              // 1024
#define F_SMEM_TOTAL (F_BE_OFF + 1024)            // 78848

// One pass over 32 rows x 32 cols x 256 k of a 128-row fp16 A in smem.
// PF: register double-buffer of B fragments, LDGs issued with max lead.
template <bool PF>
__device__ __forceinline__ void gemm_tile(float acc[2][4][4], uint32_t lm0, uint32_t lm1,
                                          const uint4* __restrict__ frag, int tpBase) {
    #pragma unroll
    for (int mi = 0; mi < 2; ++mi)
        #pragma unroll
        for (int t = 0; t < 4; ++t)
            #pragma unroll
            for (int q = 0; q < 4; ++q) acc[mi][t][q] = 0.0f;

    const uint4* fp = frag + (size_t)tpBase * 32 + (threadIdx.x & 31);
    uint4 bf0, bf1;
    if (PF) { bf0 = __ldg(fp); bf1 = __ldg(fp + 32); }
    #pragma unroll 1
    for (int kt = 0; kt < 16; ++kt) {
        uint4 bn0, bn1;
        if (PF && kt < 15) { bn0 = __ldg(fp + (kt + 1) * 512); bn1 = __ldg(fp + (kt + 1) * 512 + 32); }
        if (!PF) { bf0 = __ldg(fp + kt * 512); bf1 = __ldg(fp + kt * 512 + 32); }
        unsigned a0[4], a1[4];
        ldsm_x4(a0, lm0 + kt * 32);
        ldsm_x4(a1, lm1 + kt * 32);
        mma16816(acc[0][0], a0, bf0.x, bf0.y);
        mma16816(acc[1][0], a1, bf0.x, bf0.y);
        mma16816(acc[0][1], a0, bf0.z, bf0.w);
        mma16816(acc[1][1], a1, bf0.z, bf0.w);
        mma16816(acc[0][2], a0, bf1.x, bf1.y);
        mma16816(acc[1][2], a1, bf1.x, bf1.y);
        mma16816(acc[0][3], a0, bf1.z, bf1.w);
        mma16816(acc[1][3], a1, bf1.z, bf1.w);
        if (PF && kt < 15) { bf0 = bn0; bf1 = bn1; }
    }
}

__global__ void __launch_bounds__(512, 2) fused_kernel(
    const float* __restrict__ key_edge,
    const float* __restrict__ bk, const float* __restrict__ be,
    const float* __restrict__ bn,
    float* __restrict__ out)
{
    extern __shared__ char sm[];
    __half* sA   = (__half*)(sm + F_SA_OFF);
    float* sSc   = (float*)(sm + F_SC_OFF);      // [2][1024]f; [0] aliases sAttn
    float* sAttn = sSc;
    float* sNP   = sSc + 1024;                   // node partials: [0..511] st1, [512..1023] st2
    float* sNode = (float*)(sm + F_ND_OFF);
    float* sBk   = (float*)(sm + F_BK_OFF);
    float* sBe   = (float*)(sm + F_BE_OFF);

    const int tid = threadIdx.x, lane = tid & 31, warp = tid >> 5;
    const int bm = blockIdx.x, b = bm >> 7;

    if (tid < 256) { sBk[tid] = bk[tid]; sBe[tid] = be[tid]; }
    float bnv = (tid < 256) ? bn[tid] : 0.0f;     // early; used only at node store

    // score-fragment prefetch (independent of smem) — issue before the barrier
    const int rw_pre = warp & 7, kh_pre = warp >> 3;
    const uint4* qf = g_qWfrag + (size_t)bm * 512 + (size_t)kh_pre * 256 + lane;
    uint4 qf0 = __ldg(qf);

    // ---- phase 1: KE (fp32 global) -> sA (fp16), 512 threads ----
    const float* keb = key_edge + (size_t)bm * (Nv * Dv);
    {
        const int r8 = tid >> 6, c4 = (tid & 63) * 4;
        #pragma unroll 4
        for (int rr = 0; rr < 128; rr += 8) {
            int row = rr + r8;
            float4 v = *(const float4*)&keb[(size_t)row * 256 + c4];
            uint2 p;
            p.x = h2pack(__floats2half2_rn(v.x, v.y));
            p.y = h2pack(__floats2half2_rn(v.z, v.w));
            *(uint2*)&sA[row * PITCH + c4] = p;
        }
    }
    __syncthreads();

    const int rowsel = (lane & 7) + ((lane >> 3) & 1) * 8;
    const int colsel = (lane >> 4) * 8;
    const uint32_t smbA = smem_u32(sA);

    // ---- phase 2: scores via MMA with pre-baked fragments, k-split ----
    // warp = rw + 8*kh : rows [rw*16, rw*16+16), k-steps [kh*8, kh*8+8)
    {
        const int rw = rw_pre, kh = kh_pre;
        uint32_t lmS = smbA + (uint32_t)(((rw * 16 + rowsel) * PITCH + colsel) * 2);
        float sc[4] = {0.0f, 0.0f, 0.0f, 0.0f};
        uint4 f = qf0;
        #pragma unroll 1
        for (int ki = 0; ki < 8; ++ki) {
            int kt = kh * 8 + ki;
            uint4 fn;
            if (ki < 7) fn = __ldg(qf + (ki + 1) * 32);
            unsigned a[4];
            ldsm_x4(a, lmS + kt * 32);
            mma16816(sc, a, f.x, f.y);   // hi
            mma16816(sc, a, f.z, f.w);   // lo
            if (ki < 7) f = fn;
        }
        int rD = rw * 16 + (lane >> 2);
        int hD = (lane & 3) * 2;
        float* dst = sSc + kh * 1024;
        dst[hD * 128 + rD]           = sc[0];
        dst[(hD + 1) * 128 + rD]     = sc[1];
        dst[hD * 128 + rD + 8]       = sc[2];
        dst[(hD + 1) * 128 + rD + 8] = sc[3];
    }
    __syncthreads();

    // ---- softmax (warps 0..7, head = warp) — sums the two k-partials ----
    if (warp < 8) {
        int h = warp;
        float s[4];
        #pragma unroll
        for (int i = 0; i < 4; ++i)
            s[i] = sSc[h * 128 + lane + 32 * i] + sSc[1024 + h * 128 + lane + 32 * i];
        float mx = fmaxf(fmaxf(s[0], s[1]), fmaxf(s[2], s[3]));
        #pragma unroll
        for (int off = 16; off > 0; off >>= 1)
            mx = fmaxf(mx, __shfl_xor_sync(0xffffffffu, mx, off));
        float e[4], sum = 0.0f;
        #pragma unroll
        for (int i = 0; i < 4; ++i) { e[i] = __expf(s[i] - mx); sum += e[i]; }
        #pragma unroll
        for (int off = 16; off > 0; off >>= 1)
            sum += __shfl_xor_sync(0xffffffffu, sum, off);
        float inv = __fdividef(1.0f, sum);
        #pragma unroll
        for (int i = 0; i < 4; ++i) sAttn[h * 128 + lane + 32 * i] = e[i] * inv;
    }
    __syncthreads();

    // ---- node path, stage 1: attn @ vproj, 512 threads (2 n-halves) ----
    {
        int d = tid & 255, hh = tid >> 8;
        int h = d >> 5;
        const __half2* vp = g_vprojP + (size_t)b * 64 * 256 + d + (size_t)hh * 32 * 256;
        const float* att = &sAttn[h * 128 + hh * 64];
        float accN = 0.0f;
        #pragma unroll 8
        for (int n2 = 0; n2 < 32; ++n2) {
            float2 v = __half22float2(vp[n2 * 256]);
            accN += att[2 * n2] * v.x + att[2 * n2 + 1] * v.y;
        }
        sNP[hh * 256 + d] = accN;
    }
    __syncthreads();
    if (tid < 256) sNode[tid] = sNP[tid] + sNP[256 + tid];
    __syncthreads();
    // ---- node path, stage 2: node @ Wn^T, 512 threads (2 j-halves) ----
    {
        int d = tid & 255, hh = tid >> 8;
        const __half2* wp = g_WnTp + (size_t)hh * 64 * 256 + d;
        const float* nd = sNode + hh * 128;
        float acc2 = 0.0f;
        #pragma unroll 8
        for (int j2 = 0; j2 < 64; ++j2) {
            float2 w = __half22float2(wp[j2 * 256]);
            acc2 += nd[2 * j2] * w.x + nd[2 * j2 + 1] * w.y;
        }
        sNP[512 + hh * 256 + d] = acc2;
    }
    __syncthreads();
    if (tid < 256)
        out[EDGE_ELEMS + (size_t)bm * 256 + tid] =
            mishf(sNP[512 + tid] + sNP[768 + tid] + bnv);

    // ---- GEMM setup: 16 warps, tile = 32 rows x 32 cols ----
    const int wi = warp & 3;                 // m-band: rows [wi*32, wi*32+32)
    const int wj = warp >> 2;                // n-group: cols [wj*32, wj*32+32) per np
    const int rA = lane >> 2;
    const int kq = (lane & 3) * 2;
    const uint32_t lm0 = smbA + (uint32_t)(((wi * 32 + rowsel) * PITCH + colsel) * 2);
    const uint32_t lm1 = lm0 + 16 * PITCH * 2;

    float acc[2][4][4];
    unsigned pk0[2][4][2];

    // ---- GEMM1 np=0 (prefetched) ----
    gemm_tile<true>(acc, lm0, lm1, g_fragK4, 0 * 8 + wj * 2);
    #pragma unroll
    for (int mi = 0; mi < 2; ++mi) {
        #pragma unroll
        for (int t = 0; t < 4; ++t) {
            int r0 = wi * 32 + mi * 16 + rA;
            int c  = wj * 32 + t * 8 + kq;
            float b0 = sBk[c], b1 = sBk[c + 1];
            const float* attc = &sAttn[(c >> 5) * 128];
            float a0 = attc[r0], a8 = attc[r0 + 8];
            pk0[mi][t][0] = h2pack(__floats2half2_rn((acc[mi][t][0] + b0) * a0, (acc[mi][t][1] + b1) * a0));
            pk0[mi][t][1] = h2pack(__floats2half2_rn((acc[mi][t][2] + b0) * a8, (acc[mi][t][3] + b1) * a8));
        }
    }

    // ---- GEMM1 np=1 (no prefetch: pk0 live) ----
    gemm_tile<false>(acc, lm0, lm1, g_fragK4, 1 * 8 + wj * 2);
    __syncthreads();   // all ldmatrix reads of sA (KE) complete

    // write A2 = scaled k (fp16) over sA
    #pragma unroll
    for (int mi = 0; mi < 2; ++mi) {
        #pragma unroll
        for (int t = 0; t < 4; ++t) {
            int r0 = wi * 32 + mi * 16 + rA;
            int c0 = wj * 32 + t * 8 + kq;
            int c1 = 128 + c0;
            *(unsigned*)&sA[r0 * PITCH + c0]       = pk0[mi][t][0];
            *(unsigned*)&sA[(r0 + 8) * PITCH + c0] = pk0[mi][t][1];
            float b0 = sBk[c1], b1 = sBk[c1 + 1];
            const float* attc = &sAttn[(c1 >> 5) * 128];
            float a0 = attc[r0], a8 = attc[r0 + 8];
            *(unsigned*)&sA[r0 * PITCH + c1] =
                h2pack(__floats2half2_rn((acc[mi][t][0] + b0) * a0, (acc[mi][t][1] + b1) * a0));
            *(unsigned*)&sA[(r0 + 8) * PITCH + c1] =
                h2pack(__floats2half2_rn((acc[mi][t][2] + b0) * a8, (acc[mi][t][3] + b1) * a8));
        }
    }
    __syncthreads();   // A2 visible to all warps

    // ---- GEMM2: out = mish(A2 @ We^T + be) ----
    #pragma unroll 1
    for (int np = 0; np < 2; ++np) {
        gemm_tile<true>(acc, lm0, lm1, g_fragE4, np * 8 + wj * 2);
        #pragma unroll
        for (int mi = 0; mi < 2; ++mi) {
            #pragma unroll
            for (int t = 0; t < 4; ++t) {
                int r0 = wi * 32 + mi * 16 + rA;
                int c  = np * 128 + wj * 32 + t * 8 + kq;
                float b0 = sBe[c], b1 = sBe[c + 1];
                size_t gr = ((size_t)bm * 128 + r0) * 256 + c;
                float2 o0, o1;
                o0.x = mishf(acc[mi][t][0] + b0);
                o0.y = mishf(acc[mi][t][1] + b1);
                o1.x = mishf(acc[mi][t][2] + b0);
                o1.y = mishf(acc[mi][t][3] + b1);
                *(float2*)&out[gr]           = o0;
                *(float2*)&out[gr + 8 * 256] = o1;
            }
        }
    }
}

// ---------------------------------------------------------------------------
extern "C" void kernel_launch(void* const* d_in, const int* in_sizes, int n_in,
                              void* d_out, int out_size) {
    (void)in_sizes; (void)n_in; (void)out_size;
    const float* qn = (const float*)d_in[0];
    const float* vn = (const float*)d_in[1];
    const float* ke = (const float*)d_in[2];
    const float* Wq = (const float*)d_in[4];
    const float* bq = (const float*)d_in[5];
    const float* Wk = (const float*)d_in[6];
    const float* bk = (const float*)d_in[7];
    const float* Wv = (const float*)d_in[8];
    const float* bv = (const float*)d_in[9];
    const float* We = (const float*)d_in[10];
    const float* be = (const float*)d_in[11];
    const float* Wn = (const float*)d_in[12];
    const float* bn = (const float*)d_in[13];
    float* out = (float*)d_out;

    wprep_a_kernel<<<256, 256>>>(Wq, Wv, Wn);
    wprep_b_kernel<<<64, 256>>>(Wk, We);
    prep2_kernel<<<256, 256>>>(qn, vn, Wk, bq, bv);

    cudaFuncSetAttribute(fused_kernel, cudaFuncAttributeMaxDynamicSharedMemorySize, F_SMEM_TOTAL);
    fused_kernel<<<BM, 512, F_SMEM_TOTAL>>>(ke, bk, be, bn, out);
}

// round 16
// speedup vs baseline: 1.3841x; 1.3841x over previous
#include <cuda_runtime.h>
#include <cuda_fp16.h>
#include <math.h>
#include <stdint.h>

// ---------------- problem constants ----------------
#define Bv 16
#define Nv 128
#define Dv 256
#define Hv 8
#define BM (Bv*Nv)                               // 2048 (b,m) pairs
#define EDGE_ELEMS ((size_t)Bv*Nv*Nv*Dv)         // 67108864
#define INV_SQRT_DK 0.17677669529663688f

// ---------------- device scratch (no runtime alloc) ----------------
__device__ float g_WqT[Dv*Dv];
__device__ float g_WvT[Dv*Dv];
__device__ uint4 g_qWfrag[(size_t)BM*512];        // per-bm hi/lo score B fragments
__device__ __half2 g_vprojP[(size_t)Bv*64*Dv];    // n-paired half2: [b*64+n2][d]
__device__ __half2 g_WnTp[128*Dv];                // j-paired half2: [j2][d]
// B fragments as tile-pairs: [(kt*16 + tp)*32 + lane] = (t0.b0,t0.b1,t1.b0,t1.b1)
__device__ uint4 g_fragK4[16*16*32];
__device__ uint4 g_fragE4[16*16*32];

// fast exact-identity mish: x*tanh(log1p(e^x)) == x*(u^2-1)/(u^2+1), u=1+e^x
__device__ __forceinline__ float mishf(float x) {
    if (x > 20.0f) return x;
    float t  = __expf(x);
    float u  = 1.0f + t;
    float u2 = u * u;
    return x * __fdividef(u2 - 1.0f, u2 + 1.0f);
}
__device__ __forceinline__ unsigned h2u(__half a, __half b) {
    return (unsigned)__half_as_ushort(a) | ((unsigned)__half_as_ushort(b) << 16);
}
__device__ __forceinline__ unsigned h2pack(__half2 h) {
    return *reinterpret_cast<unsigned*>(&h);
}
__device__ __forceinline__ uint32_t smem_u32(const void* p) {
    uint32_t a;
    asm("{ .reg .u64 t; cvta.to.shared.u64 t, %1; cvt.u32.u64 %0, t; }" : "=r"(a) : "l"(p));
    return a;
}
__device__ __forceinline__ void mma16816(float* d, const unsigned* a,
                                         unsigned b0, unsigned b1) {
    asm volatile(
        "mma.sync.aligned.m16n8k16.row.col.f32.f16.f16.f32 "
        "{%0,%1,%2,%3},{%4,%5,%6,%7},{%8,%9},{%0,%1,%2,%3};"
        : "+f"(d[0]), "+f"(d[1]), "+f"(d[2]), "+f"(d[3])
        : "r"(a[0]), "r"(a[1]), "r"(a[2]), "r"(a[3]), "r"(b0), "r"(b1));
}
__device__ __forceinline__ void ldsm_x4(unsigned* a, uint32_t addr) {
    asm volatile("ldmatrix.sync.aligned.m8n8.x4.shared.b16 {%0,%1,%2,%3}, [%4];"
        : "=r"(a[0]), "=r"(a[1]), "=r"(a[2]), "=r"(a[3]) : "r"(addr));
}
__device__ __forceinline__ void hl_split(float x0, float x1, unsigned& hi, unsigned& lo) {
    __half2 h = __floats2half2_rn(x0, x1);
    float2 r = __half22float2(h);
    __half2 l = __floats2half2_rn(x0 - r.x, x1 - r.y);
    hi = h2pack(h); lo = h2pack(l);
}
// streaming (evict-first) stores for write-once output
__device__ __forceinline__ void stcs2(float* p, float2 v) {
    asm volatile("st.global.cs.v2.f32 [%0], {%1, %2};" :: "l"(p), "f"(v.x), "f"(v.y) : "memory");
}
__device__ __forceinline__ void stcs1(float* p, float v) {
    asm volatile("st.global.cs.f32 [%0], %1;" :: "l"(p), "f"(v) : "memory");
}

// ---------------- K1a: transposes + Wn pack (256 blocks x 256) ----------------
__global__ void wprep_a_kernel(const float* __restrict__ Wq, const float* __restrict__ Wv,
                               const float* __restrict__ Wn) {
    int blk = blockIdx.x, tid = threadIdx.x;
    if (blk < 128) {
        int which = blk >> 6, t2 = blk & 63;
        const float* src = (which == 0) ? Wq : Wv;
        float* dst = (which == 0) ? g_WqT : g_WvT;
        __shared__ float t[32][33];
        int x0 = (t2 & 7) * 32, y0 = (t2 >> 3) * 32;
        int tx = tid & 31, ty = tid >> 5;
        #pragma unroll
        for (int i = 0; i < 32; i += 8) t[ty + i][tx] = src[(y0 + ty + i) * Dv + x0 + tx];
        __syncthreads();
        #pragma unroll
        for (int i = 0; i < 32; i += 8) dst[(x0 + ty + i) * Dv + y0 + tx] = t[tx][ty + i];
    } else {
        int e = (blk - 128) * 256 + tid;          // 0..32767
        int j2 = e >> 8, d = e & 255;
        g_WnTp[e] = __floats2half2_rn(Wn[d * Dv + 2 * j2], Wn[d * Dv + 2 * j2 + 1]);
    }
}

// ---------------- K1b: Wk/We MMA fragments (64 blocks x 256) ----------------
__global__ void wprep_b_kernel(const float* __restrict__ Wk, const float* __restrict__ We) {
    int g = blockIdx.x * 256 + threadIdx.x;       // 0..16383
    int mat = g >> 13;
    int r = g & 8191;
    int kt = r >> 9, tp = (r >> 5) & 15, lane = r & 31;
    const float* W = mat ? We : Wk;
    int k0 = kt * 16 + (lane & 3) * 2;
    int n0 = (2 * tp) * 8 + (lane >> 2);
    int n1 = n0 + 8;
    uint4 f;
    f.x = h2u(__float2half_rn(W[n0 * Dv + k0]),     __float2half_rn(W[n0 * Dv + k0 + 1]));
    f.y = h2u(__float2half_rn(W[n0 * Dv + k0 + 8]), __float2half_rn(W[n0 * Dv + k0 + 9]));
    f.z = h2u(__float2half_rn(W[n1 * Dv + k0]),     __float2half_rn(W[n1 * Dv + k0 + 1]));
    f.w = h2u(__float2half_rn(W[n1 * Dv + k0 + 8]), __float2half_rn(W[n1 * Dv + k0 + 9]));
    if (mat) g_fragE4[r] = f;
    else     g_fragK4[r] = f;
}

// ---------------- K2: q/v projections + qW score fragments (128 CTAs x 16 bm) ----------------
__global__ void __launch_bounds__(256) prep2_kernel(
    const float* __restrict__ qn, const float* __restrict__ vn,
    const float* __restrict__ Wk,
    const float* __restrict__ bq, const float* __restrict__ bv)
{
    __shared__ float sIn[16 * 256];
    __shared__ float sQp[16 * 256];
    int tid = threadIdx.x;
    int bm0 = blockIdx.x * 16;

    // q projection (16 rows)
    for (int e = tid; e < 16 * 256; e += 256) sIn[e] = qn[(size_t)bm0 * 256 + e];
    __syncthreads();
    {
        float acc[16];
        float bqv = bq[tid];
        #pragma unroll
        for (int r = 0; r < 16; ++r) acc[r] = bqv;
        #pragma unroll 8
        for (int j = 0; j < 256; ++j) {
            float w = g_WqT[j * 256 + tid];
            #pragma unroll
            for (int r = 0; r < 16; ++r) acc[r] += sIn[r * 256 + j] * w;
        }
        #pragma unroll
        for (int r = 0; r < 16; ++r) sQp[r * 256 + tid] = acc[r];
    }
    __syncthreads();
    // v projection -> packed half2 pairs
    for (int e = tid; e < 16 * 256; e += 256) sIn[e] = vn[(size_t)bm0 * 256 + e];
    __syncthreads();
    {
        float acc[16];
        float bvv = bv[tid];
        #pragma unroll
        for (int r = 0; r < 16; ++r) acc[r] = bvv;
        #pragma unroll 8
        for (int j = 0; j < 256; ++j) {
            float w = g_WvT[j * 256 + tid];
            #pragma unroll
            for (int r = 0; r < 16; ++r) acc[r] += sIn[r * 256 + j] * w;
        }
        int b = bm0 >> 7, n2base = (bm0 & 127) >> 1;
        #pragma unroll
        for (int i = 0; i < 8; ++i)
            g_vprojP[((size_t)b * 64 + n2base + i) * 256 + tid] =
                __floats2half2_rn(acc[2 * i], acc[2 * i + 1]);
    }
    // qW fold per head -> transpose via sIn -> emit score fragments directly
    #pragma unroll 1
    for (int h = 0; h < 8; ++h) {
        float acc[16];
        #pragma unroll
        for (int r = 0; r < 16; ++r) acc[r] = 0.0f;
        #pragma unroll 8
        for (int dk = 0; dk < 32; ++dk) {
            float w = Wk[(h * 32 + dk) * 256 + tid];
            #pragma unroll
            for (int r = 0; r < 16; ++r) acc[r] += sQp[r * 256 + h * 32 + dk] * w;
        }
        __syncthreads();   // prior sIn readers (fragment step of h-1) done
        #pragma unroll
        for (int r = 0; r < 16; ++r) sIn[r * 256 + tid] = acc[r] * INV_SQRT_DK;
        __syncthreads();
        // 1024 fragment entries for this head (64 per bm: 16 kt x 4 lanes)
        #pragma unroll
        for (int i = 0; i < 4; ++i) {
            int e = tid + i * 256;            // 0..1023
            int bmr = e >> 6, rem = e & 63;
            int kt = rem >> 2, lq = rem & 3;
            int k0 = kt * 16 + lq * 2;
            const float* qh = &sIn[bmr * 256];
            uint4 f;
            hl_split(qh[k0],     qh[k0 + 1], f.x, f.z);
            hl_split(qh[k0 + 8], qh[k0 + 9], f.y, f.w);
            g_qWfrag[(size_t)(bm0 + bmr) * 512 + kt * 32 + 4 * h + lq] = f;
        }
    }
}

// ---------------- K3: fused main kernel: 2048 CTAs x 512 threads, 2 CTAs/SM ----------------
#define PITCH 264
#define F_SA_OFF   0                              // 128*264*2 = 67584
#define F_SC_OFF   67584                          // 8192: [0..4K) sAttn/partial0, [4K..8K) partial1 / node partials
#define F_ND_OFF   (F_SC_OFF + 8192)              // 1024 (combined node vector)
#define F_BK_OFF   (F_ND_OFF + 1024)              // 1024
#define F_BE_OFF   (F_BK_OFF + 1024)              // 1024
#define F_SMEM_TOTAL (F_BE_OFF + 1024)            // 78848

// One pass over 32 rows x 32 cols x 256 k of a 128-row fp16 A in smem.
// PF: register double-buffer of B fragments, LDGs issued with max lead.
template <bool PF>
__device__ __forceinline__ void gemm_tile(float acc[2][4][4], uint32_t lm0, uint32_t lm1,
                                          const uint4* __restrict__ frag, int tpBase) {
    #pragma unroll
    for (int mi = 0; mi < 2; ++mi)
        #pragma unroll
        for (int t = 0; t < 4; ++t)
            #pragma unroll
            for (int q = 0; q < 4; ++q) acc[mi][t][q] = 0.0f;

    const uint4* fp = frag + (size_t)tpBase * 32 + (threadIdx.x & 31);
    uint4 bf0, bf1;
    if (PF) { bf0 = __ldg(fp); bf1 = __ldg(fp + 32); }
    #pragma unroll 1
    for (int kt = 0; kt < 16; ++kt) {
        uint4 bn0, bn1;
        if (PF && kt < 15) { bn0 = __ldg(fp + (kt + 1) * 512); bn1 = __ldg(fp + (kt + 1) * 512 + 32); }
        if (!PF) { bf0 = __ldg(fp + kt * 512); bf1 = __ldg(fp + kt * 512 + 32); }
        unsigned a0[4], a1[4];
        ldsm_x4(a0, lm0 + kt * 32);
        ldsm_x4(a1, lm1 + kt * 32);
        mma16816(acc[0][0], a0, bf0.x, bf0.y);
        mma16816(acc[1][0], a1, bf0.x, bf0.y);
        mma16816(acc[0][1], a0, bf0.z, bf0.w);
        mma16816(acc[1][1], a1, bf0.z, bf0.w);
        mma16816(acc[0][2], a0, bf1.x, bf1.y);
        mma16816(acc[1][2], a1, bf1.x, bf1.y);
        mma16816(acc[0][3], a0, bf1.z, bf1.w);
        mma16816(acc[1][3], a1, bf1.z, bf1.w);
        if (PF && kt < 15) { bf0 = bn0; bf1 = bn1; }
    }
}

__global__ void __launch_bounds__(512, 2) fused_kernel(
    const float* __restrict__ key_edge,
    const float* __restrict__ bk, const float* __restrict__ be,
    const float* __restrict__ bn,
    float* __restrict__ out)
{
    extern __shared__ char sm[];
    __half* sA   = (__half*)(sm + F_SA_OFF);
    float* sSc   = (float*)(sm + F_SC_OFF);      // [2][1024]f; [0] aliases sAttn
    float* sAttn = sSc;
    float* sNP   = sSc + 1024;                   // node partials: [0..511] st1, [512..1023] st2
    float* sNode = (float*)(sm + F_ND_OFF);
    float* sBk   = (float*)(sm + F_BK_OFF);
    float* sBe   = (float*)(sm + F_BE_OFF);

    const int tid = threadIdx.x, lane = tid & 31, warp = tid >> 5;
    const int bm = blockIdx.x, b = bm >> 7;

    if (tid < 256) { sBk[tid] = bk[tid]; sBe[tid] = be[tid]; }
    float bnv = (tid < 256) ? bn[tid] : 0.0f;     // early; used only at node store

    // score-fragment prefetch (independent of smem) — issue before the barrier
    const int rw_pre = warp & 7, kh_pre = warp >> 3;
    const uint4* qf = g_qWfrag + (size_t)bm * 512 + (size_t)kh_pre * 256 + lane;
    uint4 qf0 = __ldg(qf);

    // ---- phase 1: KE (fp32 global) -> sA (fp16), 512 threads ----
    const float* keb = key_edge + (size_t)bm * (Nv * Dv);
    {
        const int r8 = tid >> 6, c4 = (tid & 63) * 4;
        #pragma unroll 4
        for (int rr = 0; rr < 128; rr += 8) {
            int row = rr + r8;
            float4 v = *(const float4*)&keb[(size_t)row * 256 + c4];
            uint2 p;
            p.x = h2pack(__floats2half2_rn(v.x, v.y));
            p.y = h2pack(__floats2half2_rn(v.z, v.w));
            *(uint2*)&sA[row * PITCH + c4] = p;
        }
    }
    __syncthreads();

    const int rowsel = (lane & 7) + ((lane >> 3) & 1) * 8;
    const int colsel = (lane >> 4) * 8;
    const uint32_t smbA = smem_u32(sA);

    // ---- phase 2: scores via MMA with pre-baked fragments, k-split ----
    // warp = rw + 8*kh : rows [rw*16, rw*16+16), k-steps [kh*8, kh*8+8)
    {
        const int rw = rw_pre, kh = kh_pre;
        uint32_t lmS = smbA + (uint32_t)(((rw * 16 + rowsel) * PITCH + colsel) * 2);
        float sc[4] = {0.0f, 0.0f, 0.0f, 0.0f};
        uint4 f = qf0;
        #pragma unroll 1
        for (int ki = 0; ki < 8; ++ki) {
            int kt = kh * 8 + ki;
            uint4 fn;
            if (ki < 7) fn = __ldg(qf + (ki + 1) * 32);
            unsigned a[4];
            ldsm_x4(a, lmS + kt * 32);
            mma16816(sc, a, f.x, f.y);   // hi
            mma16816(sc, a, f.z, f.w);   // lo
            if (ki < 7) f = fn;
        }
        int rD = rw * 16 + (lane >> 2);
        int hD = (lane & 3) * 2;
        float* dst = sSc + kh * 1024;
        dst[hD * 128 + rD]           = sc[0];
        dst[(hD + 1) * 128 + rD]     = sc[1];
        dst[hD * 128 + rD + 8]       = sc[2];
        dst[(hD + 1) * 128 + rD + 8] = sc[3];
    }
    __syncthreads();

    // ---- softmax (warps 0..7, head = warp) — sums the two k-partials ----
    if (warp < 8) {
        int h = warp;
        float s[4];
        #pragma unroll
        for (int i = 0; i < 4; ++i)
            s[i] = sSc[h * 128 + lane + 32 * i] + sSc[1024 + h * 128 + lane + 32 * i];
        float mx = fmaxf(fmaxf(s[0], s[1]), fmaxf(s[2], s[3]));
        #pragma unroll
        for (int off = 16; off > 0; off >>= 1)
            mx = fmaxf(mx, __shfl_xor_sync(0xffffffffu, mx, off));
        float e[4], sum = 0.0f;
        #pragma unroll
        for (int i = 0; i < 4; ++i) { e[i] = __expf(s[i] - mx); sum += e[i]; }
        #pragma unroll
        for (int off = 16; off > 0; off >>= 1)
            sum += __shfl_xor_sync(0xffffffffu, sum, off);
        float inv = __fdividef(1.0f, sum);
        #pragma unroll
        for (int i = 0; i < 4; ++i) sAttn[h * 128 + lane + 32 * i] = e[i] * inv;
    }
    __syncthreads();

    // ---- node path, stage 1: attn @ vproj, 512 threads (2 n-halves) ----
    {
        int d = tid & 255, hh = tid >> 8;
        int h = d >> 5;
        const __half2* vp = g_vprojP + (size_t)b * 64 * 256 + d + (size_t)hh * 32 * 256;
        const float* att = &sAttn[h * 128 + hh * 64];
        float accN = 0.0f;
        #pragma unroll 8
        for (int n2 = 0; n2 < 32; ++n2) {
            float2 v = __half22float2(vp[n2 * 256]);
            accN += att[2 * n2] * v.x + att[2 * n2 + 1] * v.y;
        }
        sNP[hh * 256 + d] = accN;
    }
    __syncthreads();
    if (tid < 256) sNode[tid] = sNP[tid] + sNP[256 + tid];
    __syncthreads();
    // ---- node path, stage 2: node @ Wn^T, 512 threads (2 j-halves) ----
    {
        int d = tid & 255, hh = tid >> 8;
        const __half2* wp = g_WnTp + (size_t)hh * 64 * 256 + d;
        const float* nd = sNode + hh * 128;
        float acc2 = 0.0f;
        #pragma unroll 8
        for (int j2 = 0; j2 < 64; ++j2) {
            float2 w = __half22float2(wp[j2 * 256]);
            acc2 += nd[2 * j2] * w.x + nd[2 * j2 + 1] * w.y;
        }
        sNP[512 + hh * 256 + d] = acc2;
    }
    __syncthreads();
    if (tid < 256)
        stcs1(&out[EDGE_ELEMS + (size_t)bm * 256 + tid],
              mishf(sNP[512 + tid] + sNP[768 + tid] + bnv));

    // ---- GEMM setup: 16 warps, tile = 32 rows x 32 cols ----
    const int wi = warp & 3;                 // m-band: rows [wi*32, wi*32+32)
    const int wj = warp >> 2;                // n-group: cols [wj*32, wj*32+32) per np
    const int rA = lane >> 2;
    const int kq = (lane & 3) * 2;
    const uint32_t lm0 = smbA + (uint32_t)(((wi * 32 + rowsel) * PITCH + colsel) * 2);
    const uint32_t lm1 = lm0 + 16 * PITCH * 2;

    float acc[2][4][4];
    unsigned pk0[2][4][2];

    // ---- GEMM1 np=0 (prefetched) ----
    gemm_tile<true>(acc, lm0, lm1, g_fragK4, 0 * 8 + wj * 2);
    #pragma unroll
    for (int mi = 0; mi < 2; ++mi) {
        #pragma unroll
        for (int t = 0; t < 4; ++t) {
            int r0 = wi * 32 + mi * 16 + rA;
            int c  = wj * 32 + t * 8 + kq;
            float b0 = sBk[c], b1 = sBk[c + 1];
            const float* attc = &sAttn[(c >> 5) * 128];
            float a0 = attc[r0], a8 = attc[r0 + 8];
            pk0[mi][t][0] = h2pack(__floats2half2_rn((acc[mi][t][0] + b0) * a0, (acc[mi][t][1] + b1) * a0));
            pk0[mi][t][1] = h2pack(__floats2half2_rn((acc[mi][t][2] + b0) * a8, (acc[mi][t][3] + b1) * a8));
        }
    }

    // ---- GEMM1 np=1 (no prefetch: pk0 live) ----
    gemm_tile<false>(acc, lm0, lm1, g_fragK4, 1 * 8 + wj * 2);
    __syncthreads();   // all ldmatrix reads of sA (KE) complete

    // write A2 = scaled k (fp16) over sA
    #pragma unroll
    for (int mi = 0; mi < 2; ++mi) {
        #pragma unroll
        for (int t = 0; t < 4; ++t) {
            int r0 = wi * 32 + mi * 16 + rA;
            int c0 = wj * 32 + t * 8 + kq;
            int c1 = 128 + c0;
            *(unsigned*)&sA[r0 * PITCH + c0]       = pk0[mi][t][0];
            *(unsigned*)&sA[(r0 + 8) * PITCH + c0] = pk0[mi][t][1];
            float b0 = sBk[c1], b1 = sBk[c1 + 1];
            const float* attc = &sAttn[(c1 >> 5) * 128];
            float a0 = attc[r0], a8 = attc[r0 + 8];
            *(unsigned*)&sA[r0 * PITCH + c1] =
                h2pack(__floats2half2_rn((acc[mi][t][0] + b0) * a0, (acc[mi][t][1] + b1) * a0));
            *(unsigned*)&sA[(r0 + 8) * PITCH + c1] =
                h2pack(__floats2half2_rn((acc[mi][t][2] + b0) * a8, (acc[mi][t][3] + b1) * a8));
        }
    }
    __syncthreads();   // A2 visible to all warps

    // ---- GEMM2: out = mish(A2 @ We^T + be), streaming stores ----
    #pragma unroll 1
    for (int np = 0; np < 2; ++np) {
        gemm_tile<true>(acc, lm0, lm1, g_fragE4, np * 8 + wj * 2);
        #pragma unroll
        for (int mi = 0; mi < 2; ++mi) {
            #pragma unroll
            for (int t = 0; t < 4; ++t) {
                int r0 = wi * 32 + mi * 16 + rA;
                int c  = np * 128 + wj * 32 + t * 8 + kq;
                float b0 = sBe[c], b1 = sBe[c + 1];
                size_t gr = ((size_t)bm * 128 + r0) * 256 + c;
                float2 o0, o1;
                o0.x = mishf(acc[mi][t][0] + b0);
                o0.y = mishf(acc[mi][t][1] + b1);
                o1.x = mishf(acc[mi][t][2] + b0);
                o1.y = mishf(acc[mi][t][3] + b1);
                stcs2(&out[gr],           o0);
                stcs2(&out[gr + 8 * 256], o1);
            }
        }
    }
}

// ---------------------------------------------------------------------------
extern "C" void kernel_launch(void* const* d_in, const int* in_sizes, int n_in,
                              void* d_out, int out_size) {
    (void)in_sizes; (void)n_in; (void)out_size;
    const float* qn = (const float*)d_in[0];
    const float* vn = (const float*)d_in[1];
    const float* ke = (const float*)d_in[2];
    const float* Wq = (const float*)d_in[4];
    const float* bq = (const float*)d_in[5];
    const float* Wk = (const float*)d_in[6];
    const float* bk = (const float*)d_in[7];
    const float* Wv = (const float*)d_in[8];
    const float* bv = (const float*)d_in[9];
    const float* We = (const float*)d_in[10];
    const float* be = (const float*)d_in[11];
    const float* Wn = (const float*)d_in[12];
    const float* bn = (const float*)d_in[13];
    float* out = (float*)d_out;

    wprep_a_kernel<<<256, 256>>>(Wq, Wv, Wn);
    wprep_b_kernel<<<64, 256>>>(Wk, We);
    prep2_kernel<<<128, 256>>>(qn, vn, Wk, bq, bv);

    cudaFuncSetAttribute(fused_kernel, cudaFuncAttributeMaxDynamicSharedMemorySize, F_SMEM_TOTAL);
    fused_kernel<<<BM, 512, F_SMEM_TOTAL>>>(ke, bk, be, bn, out);
}

// round 17
// speedup vs baseline: 1.5300x; 1.1055x over previous
#include <cuda_runtime.h>
#include <cuda_fp16.h>
#include <math.h>
#include <stdint.h>

// ---------------- problem constants ----------------
#define Bv 16
#define Nv 128
#define Dv 256
#define Hv 8
#define BM (Bv*Nv)                               // 2048 (b,m) pairs
#define EDGE_ELEMS ((size_t)Bv*Nv*Nv*Dv)         // 67108864
#define INV_SQRT_DK 0.17677669529663688f

// ---------------- device scratch (no runtime alloc) ----------------
__device__ float g_WqT[Dv*Dv];
__device__ float g_WvT[Dv*Dv];
__device__ uint4 g_qWfrag[(size_t)BM*512];        // per-bm hi/lo score B fragments
__device__ __half2 g_vprojP[(size_t)Bv*64*Dv];    // n-paired half2: [b*64+n2][d]
__device__ __half2 g_WnTp[128*Dv];                // j-paired half2: [j2][d]
// B fragments as tile-pairs: [(kt*16 + tp)*32 + lane] = (t0.b0,t0.b1,t1.b0,t1.b1)
__device__ uint4 g_fragK4[16*16*32];
__device__ uint4 g_fragE4[16*16*32];

// fast exact-identity mish: x*tanh(log1p(e^x)) == x*(u^2-1)/(u^2+1), u=1+e^x
__device__ __forceinline__ float mishf(float x) {
    if (x > 20.0f) return x;
    float t  = __expf(x);
    float u  = 1.0f + t;
    float u2 = u * u;
    return x * __fdividef(u2 - 1.0f, u2 + 1.0f);
}
__device__ __forceinline__ unsigned h2u(__half a, __half b) {
    return (unsigned)__half_as_ushort(a) | ((unsigned)__half_as_ushort(b) << 16);
}
__device__ __forceinline__ unsigned h2pack(__half2 h) {
    return *reinterpret_cast<unsigned*>(&h);
}
__device__ __forceinline__ uint32_t smem_u32(const void* p) {
    uint32_t a;
    asm("{ .reg .u64 t; cvta.to.shared.u64 t, %1; cvt.u32.u64 %0, t; }" : "=r"(a) : "l"(p));
    return a;
}
__device__ __forceinline__ void mma16816(float* d, const unsigned* a,
                                         unsigned b0, unsigned b1) {
    asm volatile(
        "mma.sync.aligned.m16n8k16.row.col.f32.f16.f16.f32 "
        "{%0,%1,%2,%3},{%4,%5,%6,%7},{%8,%9},{%0,%1,%2,%3};"
        : "+f"(d[0]), "+f"(d[1]), "+f"(d[2]), "+f"(d[3])
        : "r"(a[0]), "r"(a[1]), "r"(a[2]), "r"(a[3]), "r"(b0), "r"(b1));
}
__device__ __forceinline__ void ldsm_x4(unsigned* a, uint32_t addr) {
    asm volatile("ldmatrix.sync.aligned.m8n8.x4.shared.b16 {%0,%1,%2,%3}, [%4];"
        : "=r"(a[0]), "=r"(a[1]), "=r"(a[2]), "=r"(a[3]) : "r"(addr));
}
__device__ __forceinline__ void hl_split(float x0, float x1, unsigned& hi, unsigned& lo) {
    __half2 h = __floats2half2_rn(x0, x1);
    float2 r = __half22float2(h);
    __half2 l = __floats2half2_rn(x0 - r.x, x1 - r.y);
    hi = h2pack(h); lo = h2pack(l);
}
// streaming (evict-first) stores for write-once output
__device__ __forceinline__ void stcs2(float* p, float2 v) {
    asm volatile("st.global.cs.v2.f32 [%0], {%1, %2};" :: "l"(p), "f"(v.x), "f"(v.y) : "memory");
}
__device__ __forceinline__ void stcs1(float* p, float v) {
    asm volatile("st.global.cs.f32 [%0], %1;" :: "l"(p), "f"(v) : "memory");
}
// streaming (evict-first) load for read-once key_edge
__device__ __forceinline__ float4 ldcs4(const float* p) {
    float4 v;
    asm volatile("ld.global.cs.v4.f32 {%0,%1,%2,%3}, [%4];"
        : "=f"(v.x), "=f"(v.y), "=f"(v.z), "=f"(v.w) : "l"(p));
    return v;
}

// ---------------- K1a: transposes + Wn pack (256 blocks x 256) ----------------
__global__ void wprep_a_kernel(const float* __restrict__ Wq, const float* __restrict__ Wv,
                               const float* __restrict__ Wn) {
    int blk = blockIdx.x, tid = threadIdx.x;
    if (blk < 128) {
        int which = blk >> 6, t2 = blk & 63;
        const float* src = (which == 0) ? Wq : Wv;
        float* dst = (which == 0) ? g_WqT : g_WvT;
        __shared__ float t[32][33];
        int x0 = (t2 & 7) * 32, y0 = (t2 >> 3) * 32;
        int tx = tid & 31, ty = tid >> 5;
        #pragma unroll
        for (int i = 0; i < 32; i += 8) t[ty + i][tx] = src[(y0 + ty + i) * Dv + x0 + tx];
        __syncthreads();
        #pragma unroll
        for (int i = 0; i < 32; i += 8) dst[(x0 + ty + i) * Dv + y0 + tx] = t[tx][ty + i];
    } else {
        int e = (blk - 128) * 256 + tid;          // 0..32767
        int j2 = e >> 8, d = e & 255;
        g_WnTp[e] = __floats2half2_rn(Wn[d * Dv + 2 * j2], Wn[d * Dv + 2 * j2 + 1]);
    }
}

// ---------------- K1b: Wk/We MMA fragments (64 blocks x 256) ----------------
__global__ void wprep_b_kernel(const float* __restrict__ Wk, const float* __restrict__ We) {
    int g = blockIdx.x * 256 + threadIdx.x;       // 0..16383
    int mat = g >> 13;
    int r = g & 8191;
    int kt = r >> 9, tp = (r >> 5) & 15, lane = r & 31;
    const float* W = mat ? We : Wk;
    int k0 = kt * 16 + (lane & 3) * 2;
    int n0 = (2 * tp) * 8 + (lane >> 2);
    int n1 = n0 + 8;
    uint4 f;
    f.x = h2u(__float2half_rn(W[n0 * Dv + k0]),     __float2half_rn(W[n0 * Dv + k0 + 1]));
    f.y = h2u(__float2half_rn(W[n0 * Dv + k0 + 8]), __float2half_rn(W[n0 * Dv + k0 + 9]));
    f.z = h2u(__float2half_rn(W[n1 * Dv + k0]),     __float2half_rn(W[n1 * Dv + k0 + 1]));
    f.w = h2u(__float2half_rn(W[n1 * Dv + k0 + 8]), __float2half_rn(W[n1 * Dv + k0 + 9]));
    if (mat) g_fragE4[r] = f;
    else     g_fragK4[r] = f;
}

// ---------------- K2: q/v projections + qW score fragments (128 CTAs x 16 bm) ----------------
__global__ void __launch_bounds__(256) prep2_kernel(
    const float* __restrict__ qn, const float* __restrict__ vn,
    const float* __restrict__ Wk,
    const float* __restrict__ bq, const float* __restrict__ bv)
{
    __shared__ float sIn[16 * 256];
    __shared__ float sQp[16 * 256];
    int tid = threadIdx.x;
    int bm0 = blockIdx.x * 16;

    // q projection (16 rows)
    for (int e = tid; e < 16 * 256; e += 256) sIn[e] = qn[(size_t)bm0 * 256 + e];
    __syncthreads();
    {
        float acc[16];
        float bqv = bq[tid];
        #pragma unroll
        for (int r = 0; r < 16; ++r) acc[r] = bqv;
        #pragma unroll 8
        for (int j = 0; j < 256; ++j) {
            float w = g_WqT[j * 256 + tid];
            #pragma unroll
            for (int r = 0; r < 16; ++r) acc[r] += sIn[r * 256 + j] * w;
        }
        #pragma unroll
        for (int r = 0; r < 16; ++r) sQp[r * 256 + tid] = acc[r];
    }
    __syncthreads();
    // v projection -> packed half2 pairs
    for (int e = tid; e < 16 * 256; e += 256) sIn[e] = vn[(size_t)bm0 * 256 + e];
    __syncthreads();
    {
        float acc[16];
        float bvv = bv[tid];
        #pragma unroll
        for (int r = 0; r < 16; ++r) acc[r] = bvv;
        #pragma unroll 8
        for (int j = 0; j < 256; ++j) {
            float w = g_WvT[j * 256 + tid];
            #pragma unroll
            for (int r = 0; r < 16; ++r) acc[r] += sIn[r * 256 + j] * w;
        }
        int b = bm0 >> 7, n2base = (bm0 & 127) >> 1;
        #pragma unroll
        for (int i = 0; i < 8; ++i)
            g_vprojP[((size_t)b * 64 + n2base + i) * 256 + tid] =
                __floats2half2_rn(acc[2 * i], acc[2 * i + 1]);
    }
    // qW fold per head -> transpose via sIn -> emit score fragments directly
    #pragma unroll 1
    for (int h = 0; h < 8; ++h) {
        float acc[16];
        #pragma unroll
        for (int r = 0; r < 16; ++r) acc[r] = 0.0f;
        #pragma unroll 8
        for (int dk = 0; dk < 32; ++dk) {
            float w = Wk[(h * 32 + dk) * 256 + tid];
            #pragma unroll
            for (int r = 0; r < 16; ++r) acc[r] += sQp[r * 256 + h * 32 + dk] * w;
        }
        __syncthreads();   // prior sIn readers (fragment step of h-1) done
        #pragma unroll
        for (int r = 0; r < 16; ++r) sIn[r * 256 + tid] = acc[r] * INV_SQRT_DK;
        __syncthreads();
        // 1024 fragment entries for this head (64 per bm: 16 kt x 4 lanes)
        #pragma unroll
        for (int i = 0; i < 4; ++i) {
            int e = tid + i * 256;            // 0..1023
            int bmr = e >> 6, rem = e & 63;
            int kt = rem >> 2, lq = rem & 3;
            int k0 = kt * 16 + lq * 2;
            const float* qh = &sIn[bmr * 256];
            uint4 f;
            hl_split(qh[k0],     qh[k0 + 1], f.x, f.z);
            hl_split(qh[k0 + 8], qh[k0 + 9], f.y, f.w);
            g_qWfrag[(size_t)(bm0 + bmr) * 512 + kt * 32 + 4 * h + lq] = f;
        }
    }
}

// ---------------- K3: fused main kernel: 2048 CTAs x 512 threads, 2 CTAs/SM ----------------
#define PITCH 264
#define F_SA_OFF   0                              // 128*264*2 = 67584
#define F_SC_OFF   67584                          // 8192: [0..4K) sAttn/partial0, [4K..8K) partial1 / node partials
#define F_ND_OFF   (F_SC_OFF + 8192)              // 1024 (combined node vector)
#define F_BK_OFF   (F_ND_OFF + 1024)              // 1024
#define F_BE_OFF   (F_BK_OFF + 1024)              // 1024
#define F_SMEM_TOTAL (F_BE_OFF + 1024)            // 78848

// One pass over 32 rows x 32 cols x 256 k of a 128-row fp16 A in smem.
// PF: register double-buffer of B fragments, LDGs issued with max lead.
template <bool PF>
__device__ __forceinline__ void gemm_tile(float acc[2][4][4], uint32_t lm0, uint32_t lm1,
                                          const uint4* __restrict__ frag, int tpBase) {
    #pragma unroll
    for (int mi = 0; mi < 2; ++mi)
        #pragma unroll
        for (int t = 0; t < 4; ++t)
            #pragma unroll
            for (int q = 0; q < 4; ++q) acc[mi][t][q] = 0.0f;

    const uint4* fp = frag + (size_t)tpBase * 32 + (threadIdx.x & 31);
    uint4 bf0, bf1;
    if (PF) { bf0 = __ldg(fp); bf1 = __ldg(fp + 32); }
    #pragma unroll 1
    for (int kt = 0; kt < 16; ++kt) {
        uint4 bn0, bn1;
        if (PF && kt < 15) { bn0 = __ldg(fp + (kt + 1) * 512); bn1 = __ldg(fp + (kt + 1) * 512 + 32); }
        if (!PF) { bf0 = __ldg(fp + kt * 512); bf1 = __ldg(fp + kt * 512 + 32); }
        unsigned a0[4], a1[4];
        ldsm_x4(a0, lm0 + kt * 32);
        ldsm_x4(a1, lm1 + kt * 32);
        mma16816(acc[0][0], a0, bf0.x, bf0.y);
        mma16816(acc[1][0], a1, bf0.x, bf0.y);
        mma16816(acc[0][1], a0, bf0.z, bf0.w);
        mma16816(acc[1][1], a1, bf0.z, bf0.w);
        mma16816(acc[0][2], a0, bf1.x, bf1.y);
        mma16816(acc[1][2], a1, bf1.x, bf1.y);
        mma16816(acc[0][3], a0, bf1.z, bf1.w);
        mma16816(acc[1][3], a1, bf1.z, bf1.w);
        if (PF && kt < 15) { bf0 = bn0; bf1 = bn1; }
    }
}

__global__ void __launch_bounds__(512, 2) fused_kernel(
    const float* __restrict__ key_edge,
    const float* __restrict__ bk, const float* __restrict__ be,
    const float* __restrict__ bn,
    float* __restrict__ out)
{
    extern __shared__ char sm[];
    __half* sA   = (__half*)(sm + F_SA_OFF);
    float* sSc   = (float*)(sm + F_SC_OFF);      // [2][1024]f; [0] aliases sAttn
    float* sAttn = sSc;
    float* sNP   = sSc + 1024;                   // node partials: [0..511] st1, [512..1023] st2
    float* sNode = (float*)(sm + F_ND_OFF);
    float* sBk   = (float*)(sm + F_BK_OFF);
    float* sBe   = (float*)(sm + F_BE_OFF);

    const int tid = threadIdx.x, lane = tid & 31, warp = tid >> 5;
    const int bm = blockIdx.x, b = bm >> 7;

    if (tid < 256) { sBk[tid] = bk[tid]; sBe[tid] = be[tid]; }
    float bnv = (tid < 256) ? bn[tid] : 0.0f;     // early; used only at node store

    // score-fragment prefetch (independent of smem) — issue before the barrier
    const int rw_pre = warp & 7, kh_pre = warp >> 3;
    const uint4* qf = g_qWfrag + (size_t)bm * 512 + (size_t)kh_pre * 256 + lane;
    uint4 qf0 = __ldg(qf);

    // ---- phase 1: KE (fp32 global, streaming) -> sA (fp16), 512 threads ----
    const float* keb = key_edge + (size_t)bm * (Nv * Dv);
    {
        const int r8 = tid >> 6, c4 = (tid & 63) * 4;
        #pragma unroll 4
        for (int rr = 0; rr < 128; rr += 8) {
            int row = rr + r8;
            float4 v = ldcs4(&keb[(size_t)row * 256 + c4]);
            uint2 p;
            p.x = h2pack(__floats2half2_rn(v.x, v.y));
            p.y = h2pack(__floats2half2_rn(v.z, v.w));
            *(uint2*)&sA[row * PITCH + c4] = p;
        }
    }
    __syncthreads();

    const int rowsel = (lane & 7) + ((lane >> 3) & 1) * 8;
    const int colsel = (lane >> 4) * 8;
    const uint32_t smbA = smem_u32(sA);

    // ---- phase 2: scores via MMA with pre-baked fragments, k-split ----
    // warp = rw + 8*kh : rows [rw*16, rw*16+16), k-steps [kh*8, kh*8+8)
    {
        const int rw = rw_pre, kh = kh_pre;
        uint32_t lmS = smbA + (uint32_t)(((rw * 16 + rowsel) * PITCH + colsel) * 2);
        float sc[4] = {0.0f, 0.0f, 0.0f, 0.0f};
        uint4 f = qf0;
        #pragma unroll 1
        for (int ki = 0; ki < 8; ++ki) {
            int kt = kh * 8 + ki;
            uint4 fn;
            if (ki < 7) fn = __ldg(qf + (ki + 1) * 32);
            unsigned a[4];
            ldsm_x4(a, lmS + kt * 32);
            mma16816(sc, a, f.x, f.y);   // hi
            mma16816(sc, a, f.z, f.w);   // lo
            if (ki < 7) f = fn;
        }
        int rD = rw * 16 + (lane >> 2);
        int hD = (lane & 3) * 2;
        float* dst = sSc + kh * 1024;
        dst[hD * 128 + rD]           = sc[0];
        dst[(hD + 1) * 128 + rD]     = sc[1];
        dst[hD * 128 + rD + 8]       = sc[2];
        dst[(hD + 1) * 128 + rD + 8] = sc[3];
    }
    __syncthreads();

    // ---- softmax (warps 0..7, head = warp) — sums the two k-partials ----
    if (warp < 8) {
        int h = warp;
        float s[4];
        #pragma unroll
        for (int i = 0; i < 4; ++i)
            s[i] = sSc[h * 128 + lane + 32 * i] + sSc[1024 + h * 128 + lane + 32 * i];
        float mx = fmaxf(fmaxf(s[0], s[1]), fmaxf(s[2], s[3]));
        #pragma unroll
        for (int off = 16; off > 0; off >>= 1)
            mx = fmaxf(mx, __shfl_xor_sync(0xffffffffu, mx, off));
        float e[4], sum = 0.0f;
        #pragma unroll
        for (int i = 0; i < 4; ++i) { e[i] = __expf(s[i] - mx); sum += e[i]; }
        #pragma unroll
        for (int off = 16; off > 0; off >>= 1)
            sum += __shfl_xor_sync(0xffffffffu, sum, off);
        float inv = __fdividef(1.0f, sum);
        #pragma unroll
        for (int i = 0; i < 4; ++i) sAttn[h * 128 + lane + 32 * i] = e[i] * inv;
    }
    __syncthreads();

    // ---- node path, stage 1: attn @ vproj, 512 threads (2 n-halves) ----
    {
        int d = tid & 255, hh = tid >> 8;
        int h = d >> 5;
        const __half2* vp = g_vprojP + (size_t)b * 64 * 256 + d + (size_t)hh * 32 * 256;
        const float* att = &sAttn[h * 128 + hh * 64];
        float accN = 0.0f;
        #pragma unroll 8
        for (int n2 = 0; n2 < 32; ++n2) {
            float2 v = __half22float2(vp[n2 * 256]);
            accN += att[2 * n2] * v.x + att[2 * n2 + 1] * v.y;
        }
        sNP[hh * 256 + d] = accN;
    }
    __syncthreads();
    if (tid < 256) sNode[tid] = sNP[tid] + sNP[256 + tid];
    __syncthreads();
    // ---- node path, stage 2: node @ Wn^T, 512 threads (2 j-halves) ----
    {
        int d = tid & 255, hh = tid >> 8;
        const __half2* wp = g_WnTp + (size_t)hh * 64 * 256 + d;
        const float* nd = sNode + hh * 128;
        float acc2 = 0.0f;
        #pragma unroll 8
        for (int j2 = 0; j2 < 64; ++j2) {
            float2 w = __half22float2(wp[j2 * 256]);
            acc2 += nd[2 * j2] * w.x + nd[2 * j2 + 1] * w.y;
        }
        sNP[512 + hh * 256 + d] = acc2;
    }
    __syncthreads();
    if (tid < 256)
        stcs1(&out[EDGE_ELEMS + (size_t)bm * 256 + tid],
              mishf(sNP[512 + tid] + sNP[768 + tid] + bnv));

    // ---- GEMM setup: 16 warps, tile = 32 rows x 32 cols ----
    const int wi = warp & 3;                 // m-band: rows [wi*32, wi*32+32)
    const int wj = warp >> 2;                // n-group: cols [wj*32, wj*32+32) per np
    const int rA = lane >> 2;
    const int kq = (lane & 3) * 2;
    const uint32_t lm0 = smbA + (uint32_t)(((wi * 32 + rowsel) * PITCH + colsel) * 2);
    const uint32_t lm1 = lm0 + 16 * PITCH * 2;

    float acc[2][4][4];
    unsigned pk0[2][4][2];

    // ---- GEMM1 np=0 (prefetched) ----
    gemm_tile<true>(acc, lm0, lm1, g_fragK4, 0 * 8 + wj * 2);
    #pragma unroll
    for (int mi = 0; mi < 2; ++mi) {
        #pragma unroll
        for (int t = 0; t < 4; ++t) {
            int r0 = wi * 32 + mi * 16 + rA;
            int c  = wj * 32 + t * 8 + kq;
            float b0 = sBk[c], b1 = sBk[c + 1];
            const float* attc = &sAttn[(c >> 5) * 128];
            float a0 = attc[r0], a8 = attc[r0 + 8];
            pk0[mi][t][0] = h2pack(__floats2half2_rn((acc[mi][t][0] + b0) * a0, (acc[mi][t][1] + b1) * a0));
            pk0[mi][t][1] = h2pack(__floats2half2_rn((acc[mi][t][2] + b0) * a8, (acc[mi][t][3] + b1) * a8));
        }
    }

    // ---- GEMM1 np=1 (no prefetch: pk0 live) ----
    gemm_tile<false>(acc, lm0, lm1, g_fragK4, 1 * 8 + wj * 2);
    __syncthreads();   // all ldmatrix reads of sA (KE) complete

    // write A2 = scaled k (fp16) over sA
    #pragma unroll
    for (int mi = 0; mi < 2; ++mi) {
        #pragma unroll
        for (int t = 0; t < 4; ++t) {
            int r0 = wi * 32 + mi * 16 + rA;
            int c0 = wj * 32 + t * 8 + kq;
            int c1 = 128 + c0;
            *(unsigned*)&sA[r0 * PITCH + c0]       = pk0[mi][t][0];
            *(unsigned*)&sA[(r0 + 8) * PITCH + c0] = pk0[mi][t][1];
            float b0 = sBk[c1], b1 = sBk[c1 + 1];
            const float* attc = &sAttn[(c1 >> 5) * 128];
            float a0 = attc[r0], a8 = attc[r0 + 8];
            *(unsigned*)&sA[r0 * PITCH + c1] =
                h2pack(__floats2half2_rn((acc[mi][t][0] + b0) * a0, (acc[mi][t][1] + b1) * a0));
            *(unsigned*)&sA[(r0 + 8) * PITCH + c1] =
                h2pack(__floats2half2_rn((acc[mi][t][2] + b0) * a8, (acc[mi][t][3] + b1) * a8));
        }
    }
    __syncthreads();   // A2 visible to all warps

    // ---- GEMM2: out = mish(A2 @ We^T + be), streaming stores ----
    #pragma unroll 1
    for (int np = 0; np < 2; ++np) {
        gemm_tile<true>(acc, lm0, lm1, g_fragE4, np * 8 + wj * 2);
        #pragma unroll
        for (int mi = 0; mi < 2; ++mi) {
            #pragma unroll
            for (int t = 0; t < 4; ++t) {
                int r0 = wi * 32 + mi * 16 + rA;
                int c  = np * 128 + wj * 32 + t * 8 + kq;
                float b0 = sBe[c], b1 = sBe[c + 1];
                size_t gr = ((size_t)bm * 128 + r0) * 256 + c;
                float2 o0, o1;
                o0.x = mishf(acc[mi][t][0] + b0);
                o0.y = mishf(acc[mi][t][1] + b1);
                o1.x = mishf(acc[mi][t][2] + b0);
                o1.y = mishf(acc[mi][t][3] + b1);
                stcs2(&out[gr],           o0);
                stcs2(&out[gr + 8 * 256], o1);
            }
        }
    }
}

// ---------------------------------------------------------------------------
extern "C" void kernel_launch(void* const* d_in, const int* in_sizes, int n_in,
                              void* d_out, int out_size) {
    (void)in_sizes; (void)n_in; (void)out_size;
    const float* qn = (const float*)d_in[0];
    const float* vn = (const float*)d_in[1];
    const float* ke = (const float*)d_in[2];
    const float* Wq = (const float*)d_in[4];
    const float* bq = (const float*)d_in[5];
    const float* Wk = (const float*)d_in[6];
    const float* bk = (const float*)d_in[7];
    const float* Wv = (const float*)d_in[8];
    const float* bv = (const float*)d_in[9];
    const float* We = (const float*)d_in[10];
    const float* be = (const float*)d_in[11];
    const float* Wn = (const float*)d_in[12];
    const float* bn = (const float*)d_in[13];
    float* out = (float*)d_out;

    wprep_a_kernel<<<256, 256>>>(Wq, Wv, Wn);
    wprep_b_kernel<<<64, 256>>>(Wk, We);
    prep2_kernel<<<128, 256>>>(qn, vn, Wk, bq, bv);

    cudaFuncSetAttribute(fused_kernel, cudaFuncAttributeMaxDynamicSharedMemorySize, F_SMEM_TOTAL);
    fused_kernel<<<BM, 512, F_SMEM_TOTAL>>>(ke, bk, be, bn, out);
}